// round 16
// baseline (speedup 1.0000x reference)
#include <cuda_runtime.h>
#include <cuda_fp16.h>
#include <cstdint>

// Problem constants (fixed by setup_inputs)
#define BB 8
#define TT 4096
#define II 1024
#define HH 1024
#define MTOT (BB * TT)          // 32768
#define NC 32                   // scan chunks
#define CL 128                  // chunk length (NC*CL == TT)

#define KC 64                   // K-chunk (64 fp16 = 128B rows)
#define NCHUNK (II / KC)        // 16
#define TILE_BYTES 16384        // pre-swizzled 128-row x 128B tile
#define STAGE_BYTES (3 * TILE_BYTES)   // x, Wz, Wh = 48KB
#define NSTAGE 3
#define SMEM_TOTAL (NSTAGE * STAGE_BYTES)   // 144KB (1 CTA/SM; epilogue needs 137KB)

// cvt grid split: x needs MTOT*II/8/256 = 16384 blocks; each W needs 512
#define CVT_XBLKS 16384
#define CVT_WBLKS 512

// ---------------- scratch (device globals; no allocation allowed) ----------------
__device__ float g_a[(size_t)MTOT * HH];   // a_t = sigmoid(-k)
__device__ float g_b[(size_t)MTOT * HH];   // b_t = sigmoid(k)*g(p)
__device__ float g_A [BB * NC * HH];
__device__ float g_Bc[BB * NC * HH];
__device__ float g_carry[BB * NC * HH];
// pre-tiled, pre-swizzled fp16 images: tile (blk, kc) at ((blk*16 + kc) * 16KB)
__device__ __half g_x16t[(size_t)MTOT * II];   // 256 m-blocks x 16 kc
__device__ __half g_wzt[HH * II];              // 8 n-blocks x 16 kc
__device__ __half g_wht[HH * II];

// ---------------- helpers ----------------
__device__ __forceinline__ uint32_t smem_u32(const void* p) {
    uint32_t a;
    asm("{ .reg .u64 t; cvta.to.shared.u64 t, %1; cvt.u32.u64 %0, t; }" : "=r"(a) : "l"(p));
    return a;
}
__device__ __forceinline__ void bulk_g2s(uint32_t dst, const void* src, uint32_t bytes, uint32_t bar) {
    asm volatile("cp.async.bulk.shared::cta.global.mbarrier::complete_tx::bytes [%0], [%1], %2, [%3];"
        :: "r"(dst), "l"(src), "r"(bytes), "r"(bar) : "memory");
}
#define MBARRIER_INIT(addr, cnt) \
    asm volatile("mbarrier.init.shared.b64 [%0], %1;" :: "r"((uint32_t)(addr)), "r"((uint32_t)(cnt)) : "memory")
#define MBARRIER_EXPECT_TX(addr, bytes) \
    asm volatile("mbarrier.arrive.expect_tx.shared.b64 _, [%0], %1;" :: "r"((uint32_t)(addr)), "r"((uint32_t)(bytes)) : "memory")
#define MBARRIER_WAIT_PARITY(addr, par) do { \
    uint32_t _m = (uint32_t)(addr); uint32_t _p = (uint32_t)(par); uint32_t _d; \
    asm volatile("{\n\t.reg .pred p;\n\tmbarrier.try_wait.parity.acquire.cta.shared::cta.b64 p, [%1], %2;\n\tselp.b32 %0, 1, 0, p;\n\t}" \
        : "=r"(_d) : "r"(_m), "r"(_p) : "memory"); \
    if (!_d) { \
        asm volatile("{\n\t.reg .pred P1;\n\tWL_%=:\n\tmbarrier.try_wait.parity.acquire.cta.shared::cta.b64 P1, [%0], %1, 0x989680;\n\t@P1 bra.uni WD_%=;\n\tbra.uni WL_%=;\n\tWD_%=:\n\t}" \
            :: "r"(_m), "r"(_p) : "memory"); \
    } } while (0)

__device__ __forceinline__ void ldsm4(uint32_t (&r)[4], uint32_t addr) {
    asm volatile("ldmatrix.sync.aligned.m8n8.x4.shared.b16 {%0,%1,%2,%3}, [%4];"
        : "=r"(r[0]), "=r"(r[1]), "=r"(r[2]), "=r"(r[3]) : "r"(addr));
}
#define MMA16816(d, a, b0v, b1v) \
    asm volatile("mma.sync.aligned.m16n8k16.row.col.f32.f16.f16.f32 " \
        "{%0,%1,%2,%3}, {%4,%5,%6,%7}, {%8,%9}, {%0,%1,%2,%3};" \
        : "+f"((d)[0]), "+f"((d)[1]), "+f"((d)[2]), "+f"((d)[3]) \
        : "r"((a)[0]), "r"((a)[1]), "r"((a)[2]), "r"((a)[3]), "r"(b0v), "r"(b1v))

__device__ __forceinline__ uint32_t sw128(uint32_t off) { return off ^ ((off >> 3) & 0x70); }

// ---- pure fixed-latency-pipe exp / rcp (keep MUFU idle) ----
__device__ __forceinline__ float fexp(float x) {           // e^x, rel err ~2e-7
    float t = x * 1.4426950408889634f;
    float fi = t + 12582912.0f;
    int i = __float_as_int(fi) - 0x4B400000;
    float f = t - (fi - 12582912.0f);
    float p = 1.5403530393381609e-4f;
    p = fmaf(p, f, 1.3333558146428443e-3f);
    p = fmaf(p, f, 9.6181291076284772e-3f);
    p = fmaf(p, f, 5.5504108664821580e-2f);
    p = fmaf(p, f, 2.4022650695910072e-1f);
    p = fmaf(p, f, 6.9314718055994531e-1f);
    p = fmaf(p, f, 1.0f);
    return __int_as_float(__float_as_int(p) + (i << 23));
}
__device__ __forceinline__ float frcp(float d) {           // 1/d, d>0 normal
    float y = __int_as_float(0x7EF311C3 - __float_as_int(d));
    y = y * (2.0f - d * y);
    y = y * (2.0f - d * y);
    y = y * (2.0f - d * y);
    return y;
}
__device__ __forceinline__ float g_fn_scan(float x) {
    return (x >= 0.0f) ? (x + 0.5f) : frcp(1.0f + fexp(-x));
}

// ---------------- cvt fp32 -> fp16, pre-tiled + pre-swizzled ----------------
// One thread handles 8 consecutive k-elements (16B output unit).
// x: blocks [0, CVT_XBLKS); Wz: next CVT_WBLKS; Wh: next CVT_WBLKS
__global__ __launch_bounds__(256)
void cvt_tile_kernel(const float* __restrict__ x, const float* __restrict__ Wz,
                     const float* __restrict__ Wh) {
    int bid = blockIdx.x;
    const float* src;
    __half* dst;
    int id;
    if (bid < CVT_XBLKS) {
        src = x;  dst = g_x16t; id = bid * 256 + threadIdx.x;
    } else if (bid < CVT_XBLKS + CVT_WBLKS) {
        src = Wz; dst = g_wzt;  id = (bid - CVT_XBLKS) * 256 + threadIdx.x;
    } else {
        src = Wh; dst = g_wht;  id = (bid - CVT_XBLKS - CVT_WBLKS) * 256 + threadIdx.x;
    }

    int m  = id >> 7;       // row
    int k8 = id & 127;      // 16B unit index along k (128 units = 1024 cols)
    const float4* p = (const float4*)(src + (size_t)m * II + k8 * 8);
    float4 v0 = p[0], v1 = p[1];

    __half2 h01 = __half2(__float2half(v0.x), __float2half(v0.y));
    __half2 h23 = __half2(__float2half(v0.z), __float2half(v0.w));
    __half2 h45 = __half2(__float2half(v1.x), __float2half(v1.y));
    __half2 h67 = __half2(__float2half(v1.z), __float2half(v1.w));
    uint4 pk;
    pk.x = *(uint32_t*)&h01; pk.y = *(uint32_t*)&h23;
    pk.z = *(uint32_t*)&h45; pk.w = *(uint32_t*)&h67;

    int blk = m >> 7, r = m & 127, kc = k8 >> 3, u = k8 & 7;
    size_t tile = ((size_t)(blk * 16 + kc)) * TILE_BYTES;
    uint32_t off = sw128((uint32_t)(r * 128 + u * 16));
    *(uint4*)((char*)dst + tile + off) = pk;
}

// ---------------- dual GEMM: bulk-copy loader + mma.sync + fused summary ----------------
__global__ __launch_bounds__(256, 1)
void gemm_mma_kernel(const float* __restrict__ bz, const float* __restrict__ bh) {
    extern __shared__ char smem[];
    __shared__ uint64_t mbar[NSTAGE];
    const uint32_t sb = smem_u32(smem);
    const int tid = threadIdx.x;
    const int lane = tid & 31;
    const int wid = tid >> 5;
    const int g = lane >> 3, lr = lane & 7;
    const int wm = (wid >> 1) * 32;     // 4 warps along M (32 rows each)
    const int wn = (wid & 1) * 64;      // 2 warps along N (64 cols each)
    const int n0 = blockIdx.x * 128;    // H block (x-fast: wave shares x tiles)
    const int m0 = blockIdx.y * 128;
    const int mb = m0 >> 7, nb = n0 >> 7;

    if (tid == 0) {
#pragma unroll
        for (int s = 0; s < NSTAGE; ++s) MBARRIER_INIT(smem_u32(&mbar[s]), 1);
    }
    __syncthreads();

    // issue chunk c's 3 tiles (48KB) into stage s
    auto issue = [&](int c, int s) {
        uint32_t bar = smem_u32(&mbar[s]);
        uint32_t dst = sb + (uint32_t)s * STAGE_BYTES;
        MBARRIER_EXPECT_TX(bar, 3 * TILE_BYTES);
        bulk_g2s(dst,                  (const char*)g_x16t + ((size_t)(mb * 16 + c)) * TILE_BYTES, TILE_BYTES, bar);
        bulk_g2s(dst + TILE_BYTES,     (const char*)g_wzt  + ((size_t)(nb * 16 + c)) * TILE_BYTES, TILE_BYTES, bar);
        bulk_g2s(dst + 2 * TILE_BYTES, (const char*)g_wht  + ((size_t)(nb * 16 + c)) * TILE_BYTES, TILE_BYTES, bar);
    };
    if (tid == 0) { issue(0, 0); issue(1, 1); }

    float acck[2][8][4], accp[2][8][4];
#pragma unroll
    for (int mt = 0; mt < 2; ++mt)
#pragma unroll
        for (int nt = 0; nt < 8; ++nt)
#pragma unroll
            for (int q = 0; q < 4; ++q) { acck[mt][nt][q] = 0.0f; accp[mt][nt][q] = 0.0f; }

    for (int c = 0; c < NCHUNK; ++c) {
        const int s = c % NSTAGE;
        MBARRIER_WAIT_PARITY(smem_u32(&mbar[s]), (c / NSTAGE) & 1);
        __syncthreads();                 // all warps finished chunk c-1 (frees stage (c+2)%3)
        if (tid == 0 && c + 2 < NCHUNK) issue(c + 2, (c + 2) % NSTAGE);

        const uint32_t st = sb + (uint32_t)s * STAGE_BYTES;
        const uint32_t sA = st;
        const uint32_t sZ = st + TILE_BYTES, sH = st + 2 * TILE_BYTES;

#pragma unroll
        for (int ks = 0; ks < 4; ++ks) {
            uint32_t af[2][4];
#pragma unroll
            for (int mt = 0; mt < 2; ++mt) {
                uint32_t off = sw128((uint32_t)((wm + mt * 16 + (g & 1) * 8 + lr) * 128 + (2 * ks + (g >> 1)) * 16));
                ldsm4(af[mt], sA + off);
            }
            uint32_t bzf[4][4], bhf[4][4];
#pragma unroll
            for (int j = 0; j < 4; ++j) {
                uint32_t off = sw128((uint32_t)((wn + j * 16 + (g >> 1) * 8 + lr) * 128 + (2 * ks + (g & 1)) * 16));
                ldsm4(bzf[j], sZ + off);
                ldsm4(bhf[j], sH + off);
            }
#pragma unroll
            for (int mt = 0; mt < 2; ++mt)
#pragma unroll
                for (int nt = 0; nt < 8; ++nt) {
                    int j = nt >> 1, h = (nt & 1) * 2;
                    MMA16816(acck[mt][nt], af[mt], bzf[j][h], bzf[j][h + 1]);
                    MMA16816(accp[mt][nt], af[mt], bhf[j][h], bhf[j][h + 1]);
                }
        }
    }
    __syncthreads();   // stages dead; smem becomes a/b planes

    // ---- epilogue: activations -> smem planes [128][132], fused chunk summary ----
    float* planeA = (float*)smem;            // 128*132 floats (67.5KB)
    float* planeB = planeA + 128 * 132;
    float* partA  = planeB + 128 * 132;      // 256
    float* partB  = partA + 256;

#pragma unroll
    for (int mt = 0; mt < 2; ++mt)
#pragma unroll
        for (int nt = 0; nt < 8; ++nt) {
            int cc = wn + nt * 8 + (lane & 3) * 2;
            float bzv0 = bz[n0 + cc], bzv1 = bz[n0 + cc + 1];
            float bhv0 = bh[n0 + cc], bhv1 = bh[n0 + cc + 1];
#pragma unroll
            for (int h = 0; h < 2; ++h) {
                int r = wm + mt * 16 + (lane >> 2) + h * 8;   // local t-row 0..127
                float kv0 = acck[mt][nt][2 * h]     + bzv0;
                float kv1 = acck[mt][nt][2 * h + 1] + bzv1;
                float pv0 = accp[mt][nt][2 * h]     + bhv0;
                float pv1 = accp[mt][nt][2 * h + 1] + bhv1;

                float e0 = fexp(kv0), e1 = fexp(kv1);
                float r0 = frcp(1.0f + e0), r1 = frcp(1.0f + e1);
                float z0 = e0 * r0, z1 = e1 * r1;       // sigmoid(k)
                float em0 = fexp(-pv0), em1 = fexp(-pv1);
                float gs0 = frcp(1.0f + em0), gs1 = frcp(1.0f + em1);
                float gg0 = (pv0 >= 0.0f) ? (pv0 + 0.5f) : gs0;
                float gg1 = (pv1 >= 0.0f) ? (pv1 + 0.5f) : gs1;

                *(float2*)(planeA + r * 132 + cc) = make_float2(r0, r1);
                *(float2*)(planeB + r * 132 + cc) = make_float2(z0 * gg0, z1 * gg1);
            }
        }
    __syncthreads();

    // ---- in-CTA chunk summary: 256 threads = 2 segments x 128 h, 64 steps each ----
    {
        const int h = tid & 127;
        const int s = tid >> 7;              // 0: rows 0..63, 1: rows 64..127
        float A = 1.0f, Bacc = 0.0f;
        const float* pa = planeA + (s * 64) * 132 + h;
        const float* pb = planeB + (s * 64) * 132 + h;
#pragma unroll 8
        for (int i = 0; i < 64; ++i) {
            float a = pa[i * 132];
            float bb = pb[i * 132];
            Bacc = fmaf(a, Bacc, bb);
            A *= a;
        }
        partA[tid] = A;
        partB[tid] = Bacc;
    }
    __syncthreads();
    if (tid < 128) {
        float A0 = partA[tid], B0 = partB[tid];
        float A1 = partA[128 + tid], B1 = partB[128 + tid];
        int b = m0 >> 12, c = (m0 >> 7) & (NC - 1);
        int idx = (b * NC + c) * HH + n0 + tid;
        g_A[idx]  = A0 * A1;
        g_Bc[idx] = fmaf(A1, B0, B1);
    }

    // ---- coalesced g_a / g_b stores: 128 rows x 32 float4 ----
#pragma unroll
    for (int pass = 0; pass < 16; ++pass) {
        int r = pass * 8 + (tid >> 5);
        int c4 = tid & 31;
        size_t grow = (size_t)(m0 + r) * HH + n0 + c4 * 4;
        *(float4*)(g_a + grow) = *(float4*)(planeA + r * 132 + c4 * 4);
        *(float4*)(g_b + grow) = *(float4*)(planeB + r * 132 + c4 * 4);
    }
}

// ---------------- scan pass 2: combine chunks ----------------
__global__ __launch_bounds__(256)
void scan_chunk_combine(const float* __restrict__ h0) {
    int idx = blockIdx.x * blockDim.x + threadIdx.x;   // (b, h)
    int h = idx & (HH - 1);
    int b = idx >> 10;
    float carry = g_fn_scan(h0[b * HH + h]);
#pragma unroll
    for (int c = 0; c < NC; ++c) {
        int s = (b * NC + c) * HH + h;
        g_carry[s] = carry;
        carry = fmaf(g_A[s], carry, g_Bc[s]);
    }
}

// ---------------- scan pass 3: apply carries, write output ----------------
__global__ __launch_bounds__(256)
void scan_apply(float* __restrict__ out) {
    int idx = blockIdx.x * blockDim.x + threadIdx.x;   // (b, c, h)
    int h = idx & (HH - 1);
    int c = (idx >> 10) & (NC - 1);
    int b = idx >> 15;
    size_t base = ((size_t)(b * TT + c * CL)) * HH + h;
    float hc = g_carry[(b * NC + c) * HH + h];
#pragma unroll 8
    for (int i = 0; i < CL; ++i) {
        float a = g_a[base + (size_t)i * HH];
        float bb = g_b[base + (size_t)i * HH];
        hc = fmaf(a, hc, bb);
        out[base + (size_t)i * HH] = hc;
    }
}

extern "C" void kernel_launch(void* const* d_in, const int* in_sizes, int n_in,
                              void* d_out, int out_size) {
    const float* x  = (const float*)d_in[0];
    const float* h0 = (const float*)d_in[1];
    const float* Wz = (const float*)d_in[2];
    const float* bz = (const float*)d_in[3];
    const float* Wh = (const float*)d_in[4];
    const float* bh = (const float*)d_in[5];
    float* out = (float*)d_out;

    cvt_tile_kernel<<<CVT_XBLKS + 2 * CVT_WBLKS, 256>>>(x, Wz, Wh);

    cudaFuncSetAttribute(gemm_mma_kernel, cudaFuncAttributeMaxDynamicSharedMemorySize, SMEM_TOTAL);
    dim3 ggrid(HH / 128, MTOT / 128);   // x = n-block (8), y = m-block (256)
    gemm_mma_kernel<<<ggrid, 256, SMEM_TOTAL>>>(bz, bh);

    scan_chunk_combine<<<(BB * HH) / 256, 256>>>(h0);
    scan_apply<<<(BB * NC * HH) / 256, 256>>>(out);
}

// round 17
// speedup vs baseline: 1.5045x; 1.5045x over previous
#include <cuda_runtime.h>
#include <cuda_fp16.h>
#include <cstdint>

// Problem constants (fixed by setup_inputs)
#define BB 8
#define TT 4096
#define II 1024
#define HH 1024
#define MTOT (BB * TT)          // 32768
#define NC 32                   // scan chunks
#define CL 128                  // chunk length (NC*CL == TT)

#define KC 64                   // K-chunk (64 fp16 = 128B rows, SW128 swizzle)
#define NCHUNK (II / KC)        // 16
#define X_BYTES (128 * 128)     // x tile: 128 rows x 128B = 16KB
#define W_BYTES (64 * 128)      // W tile: 64 rows x 128B = 8KB
#define STAGE_BYTES (X_BYTES + 2 * W_BYTES)   // 32KB
#define NSTAGE 3
#define SMEM_TOTAL (NSTAGE * STAGE_BYTES)     // 96KB -> 2 CTAs/SM

// ---------------- scratch (device globals; no allocation allowed) ----------------
__device__ float g_a[(size_t)MTOT * HH];   // a_t = sigmoid(-k)
__device__ float g_b[(size_t)MTOT * HH];   // b_t = sigmoid(k)*g(p)
__device__ float g_A [BB * NC * HH];
__device__ float g_Bc[BB * NC * HH];
__device__ float g_carry[BB * NC * HH];
__device__ __half g_x16[(size_t)MTOT * II];
__device__ __half g_wz[HH * II];
__device__ __half g_wh[HH * II];

// ---------------- helpers ----------------
__device__ __forceinline__ uint32_t smem_u32(const void* p) {
    uint32_t a;
    asm("{ .reg .u64 t; cvta.to.shared.u64 t, %1; cvt.u32.u64 %0, t; }" : "=r"(a) : "l"(p));
    return a;
}
__device__ __forceinline__ void cp16(uint32_t saddr, const void* gaddr) {
    asm volatile("cp.async.cg.shared.global [%0], [%1], 16;" :: "r"(saddr), "l"(gaddr));
}
__device__ __forceinline__ void cp_commit() { asm volatile("cp.async.commit_group;" ::: "memory"); }
template <int N>
__device__ __forceinline__ void cp_wait() { asm volatile("cp.async.wait_group %0;" :: "n"(N) : "memory"); }

__device__ __forceinline__ void ldsm4(uint32_t (&r)[4], uint32_t addr) {
    asm volatile("ldmatrix.sync.aligned.m8n8.x4.shared.b16 {%0,%1,%2,%3}, [%4];"
        : "=r"(r[0]), "=r"(r[1]), "=r"(r[2]), "=r"(r[3]) : "r"(addr));
}
#define MMA16816(d, a, b0v, b1v) \
    asm volatile("mma.sync.aligned.m16n8k16.row.col.f32.f16.f16.f32 " \
        "{%0,%1,%2,%3}, {%4,%5,%6,%7}, {%8,%9}, {%0,%1,%2,%3};" \
        : "+f"((d)[0]), "+f"((d)[1]), "+f"((d)[2]), "+f"((d)[3]) \
        : "r"((a)[0]), "r"((a)[1]), "r"((a)[2]), "r"((a)[3]), "r"(b0v), "r"(b1v))

__device__ __forceinline__ uint32_t sw128(uint32_t off) { return off ^ ((off >> 3) & 0x70); }

// ---- pure fixed-latency-pipe exp / rcp (keep MUFU idle) ----
__device__ __forceinline__ float fexp(float x) {           // e^x, rel err ~2e-7
    float t = x * 1.4426950408889634f;
    float fi = t + 12582912.0f;
    int i = __float_as_int(fi) - 0x4B400000;
    float f = t - (fi - 12582912.0f);
    float p = 1.5403530393381609e-4f;
    p = fmaf(p, f, 1.3333558146428443e-3f);
    p = fmaf(p, f, 9.6181291076284772e-3f);
    p = fmaf(p, f, 5.5504108664821580e-2f);
    p = fmaf(p, f, 2.4022650695910072e-1f);
    p = fmaf(p, f, 6.9314718055994531e-1f);
    p = fmaf(p, f, 1.0f);
    return __int_as_float(__float_as_int(p) + (i << 23));
}
__device__ __forceinline__ float frcp(float d) {           // 1/d, d>0 normal
    float y = __int_as_float(0x7EF311C3 - __float_as_int(d));
    y = y * (2.0f - d * y);
    y = y * (2.0f - d * y);
    y = y * (2.0f - d * y);
    return y;
}
__device__ __forceinline__ float g_fn_scan(float x) {
    return (x >= 0.0f) ? (x + 0.5f) : frcp(1.0f + fexp(-x));
}

// ---------------- convert fp32 -> fp16 ----------------
__global__ __launch_bounds__(256)
void cvt_kernel(const float* __restrict__ in, __half* __restrict__ out) {
    size_t i = ((size_t)blockIdx.x * blockDim.x + threadIdx.x) * 4;
    float4 v = *(const float4*)(in + i);
    *(__half2*)(out + i)     = __half2(__float2half(v.x), __float2half(v.y));
    *(__half2*)(out + i + 2) = __half2(__float2half(v.z), __float2half(v.w));
}

// ---------------- quarter-chunk loader: q=0,1 -> x halves; q=2 -> wz; q=3 -> wh ----------------
__device__ __forceinline__ void load_quarter(uint32_t sbase, int m0, int n0, int k0, int tid, int q) {
    if (q < 2) {
#pragma unroll
        for (int s = 0; s < 2; ++s) {
            int i = tid + (q * 2 + s) * 256;   // 0..1023 across q=0,1
            int r = i >> 3;
            int u = i & 7;
            const char* gp = (const char*)(g_x16 + (size_t)(m0 + r) * II + k0) + u * 16;
            uint32_t off = (uint32_t)(r * 128 + u * 16);
            cp16(sbase + sw128(off), gp);
        }
    } else {
        const __half* base = (q == 2) ? g_wz : g_wh;
        uint32_t toff = (q == 2) ? (uint32_t)X_BYTES : (uint32_t)(X_BYTES + W_BYTES);
#pragma unroll
        for (int s = 0; s < 2; ++s) {
            int i = tid + s * 256;             // 0..511 = 64 rows x 8 units
            int r = i >> 3;
            int u = i & 7;
            const char* gp = (const char*)(base + (size_t)(n0 + r) * II + k0) + u * 16;
            uint32_t off = (uint32_t)(r * 128 + u * 16);
            cp16(sbase + toff + sw128(off), gp);
        }
    }
}

// ---------------- dual GEMM via mma.sync, 128x64 tile, 2 CTAs/SM, interleaved loads ----------------
__global__ __launch_bounds__(256, 2)
void gemm_mma_kernel(const float* __restrict__ bz, const float* __restrict__ bh) {
    extern __shared__ char smem[];
    const uint32_t sb = smem_u32(smem);
    const int tid = threadIdx.x;
    const int lane = tid & 31;
    const int wid = tid >> 5;
    const int g = lane >> 3, lr = lane & 7;
    const int wm = (wid >> 1) * 32;     // 4 warps along M (32 rows each)
    const int wn = (wid & 1) * 32;      // 2 warps along N (32 cols each)
    const int n0 = blockIdx.x * 64;     // H block (x-fast: wave shares x tiles)
    const int m0 = blockIdx.y * 128;

    float acck[2][4][4], accp[2][4][4];
#pragma unroll
    for (int mt = 0; mt < 2; ++mt)
#pragma unroll
        for (int nt = 0; nt < 4; ++nt)
#pragma unroll
            for (int q = 0; q < 4; ++q) { acck[mt][nt][q] = 0.0f; accp[mt][nt][q] = 0.0f; }

    // prologue: chunks 0 and 1, as 4 quarter-groups each (8 commits total)
#pragma unroll
    for (int q = 0; q < 4; ++q) { load_quarter(sb, m0, n0, 0, tid, q); cp_commit(); }
#pragma unroll
    for (int q = 0; q < 4; ++q) { load_quarter(sb + STAGE_BYTES, m0, n0, KC, tid, q); cp_commit(); }

    for (int c = 0; c < NCHUNK; ++c) {
        // entering iter c: pending = chunk c (4 groups) + chunk c+1 (4 groups)
        if (c + 2 < NCHUNK) {
            cp_wait<4>();    // chunk c resident; chunk c+1 still in flight
        } else {
            cp_wait<0>();    // tail: drain everything
        }
        __syncthreads();     // all warps done with stage (c+2)%3 (read during iter c-1)

        const uint32_t st = sb + (c % NSTAGE) * STAGE_BYTES;
        const uint32_t sA = st;
        const uint32_t sZ = st + X_BYTES, sH = st + X_BYTES + W_BYTES;
        const bool pf = (c + 2 < NCHUNK);
        const uint32_t pfdst = sb + ((c + 2) % NSTAGE) * STAGE_BYTES;
        const int pfk = (c + 2) * KC;

#pragma unroll
        for (int ks = 0; ks < 4; ++ks) {
            uint32_t af[2][4];
#pragma unroll
            for (int mt = 0; mt < 2; ++mt) {
                uint32_t off = sw128((uint32_t)((wm + mt * 16 + (g & 1) * 8 + lr) * 128 + (2 * ks + (g >> 1)) * 16));
                ldsm4(af[mt], sA + off);
            }
            uint32_t bzf[2][4], bhf[2][4];
#pragma unroll
            for (int j = 0; j < 2; ++j) {
                uint32_t off = sw128((uint32_t)((wn + j * 16 + (g >> 1) * 8 + lr) * 128 + (2 * ks + (g & 1)) * 16));
                ldsm4(bzf[j], sZ + off);
                ldsm4(bhf[j], sH + off);
            }
#pragma unroll
            for (int mt = 0; mt < 2; ++mt)
#pragma unroll
                for (int nt = 0; nt < 4; ++nt) {
                    int j = nt >> 1, h = (nt & 1) * 2;
                    MMA16816(acck[mt][nt], af[mt], bzf[j][h], bzf[j][h + 1]);
                    MMA16816(accp[mt][nt], af[mt], bhf[j][h], bhf[j][h + 1]);
                }
            // interleaved prefetch: quarter ks of chunk c+2 (after this ks's MMAs)
            if (pf) {
                load_quarter(pfdst, m0, n0, pfk, tid, ks);
                cp_commit();
            }
        }
        __syncthreads();
    }

    // ---- epilogue: activations -> smem planes [128][68], fused chunk summary ----
    float* planeA = (float*)smem;            // 128*68 floats (34.8KB)
    float* planeB = planeA + 128 * 68;
    float* partA  = planeB + 128 * 68;       // 256
    float* partB  = partA + 256;

#pragma unroll
    for (int mt = 0; mt < 2; ++mt)
#pragma unroll
        for (int nt = 0; nt < 4; ++nt) {
            int cc = wn + nt * 8 + (lane & 3) * 2;
            float bzv0 = bz[n0 + cc], bzv1 = bz[n0 + cc + 1];
            float bhv0 = bh[n0 + cc], bhv1 = bh[n0 + cc + 1];
#pragma unroll
            for (int h = 0; h < 2; ++h) {
                int r = wm + mt * 16 + (lane >> 2) + h * 8;   // local t-row 0..127
                float kv0 = acck[mt][nt][2 * h]     + bzv0;
                float kv1 = acck[mt][nt][2 * h + 1] + bzv1;
                float pv0 = accp[mt][nt][2 * h]     + bhv0;
                float pv1 = accp[mt][nt][2 * h + 1] + bhv1;

                float e0 = fexp(kv0), e1 = fexp(kv1);
                float r0 = frcp(1.0f + e0), r1 = frcp(1.0f + e1);
                float z0 = e0 * r0, z1 = e1 * r1;       // sigmoid(k)
                float em0 = fexp(-pv0), em1 = fexp(-pv1);
                float gs0 = frcp(1.0f + em0), gs1 = frcp(1.0f + em1);
                float gg0 = (pv0 >= 0.0f) ? (pv0 + 0.5f) : gs0;
                float gg1 = (pv1 >= 0.0f) ? (pv1 + 0.5f) : gs1;

                *(float2*)(planeA + r * 68 + cc) = make_float2(r0, r1);
                *(float2*)(planeB + r * 68 + cc) = make_float2(z0 * gg0, z1 * gg1);
            }
        }
    __syncthreads();

    // ---- in-CTA chunk summary: 256 threads = 4 segments x 64 h, 32 steps each ----
    {
        const int h = tid & 63;
        const int s = tid >> 6;              // 0..3 -> rows s*32..s*32+31
        float A = 1.0f, Bacc = 0.0f;
        const float* pa = planeA + (s * 32) * 68 + h;
        const float* pb = planeB + (s * 32) * 68 + h;
#pragma unroll 8
        for (int i = 0; i < 32; ++i) {
            float a = pa[i * 68];
            float bb = pb[i * 68];
            Bacc = fmaf(a, Bacc, bb);
            A *= a;
        }
        partA[tid] = A;
        partB[tid] = Bacc;
    }
    __syncthreads();
    if (tid < 64) {
        float A0 = partA[tid],       B0 = partB[tid];
        float A1 = partA[64 + tid],  B1 = partB[64 + tid];
        float A2 = partA[128 + tid], B2 = partB[128 + tid];
        float A3 = partA[192 + tid], B3 = partB[192 + tid];
        float b01 = fmaf(A1, B0, B1);
        float b23 = fmaf(A3, B2, B3);
        int b = m0 >> 12, c = (m0 >> 7) & (NC - 1);
        int idx = (b * NC + c) * HH + n0 + tid;
        g_A[idx]  = (A0 * A1) * (A2 * A3);
        g_Bc[idx] = fmaf(A2 * A3, b01, b23);
    }

    // ---- coalesced g_a / g_b stores: 128 rows x 16 float4 ----
#pragma unroll
    for (int pass = 0; pass < 8; ++pass) {
        int r = pass * 16 + (tid >> 4);
        int c4 = tid & 15;
        size_t grow = (size_t)(m0 + r) * HH + n0 + c4 * 4;
        *(float4*)(g_a + grow) = *(float4*)(planeA + r * 68 + c4 * 4);
        *(float4*)(g_b + grow) = *(float4*)(planeB + r * 68 + c4 * 4);
    }
}

// ---------------- scan pass 2: combine chunks ----------------
__global__ __launch_bounds__(256)
void scan_chunk_combine(const float* __restrict__ h0) {
    int idx = blockIdx.x * blockDim.x + threadIdx.x;   // (b, h)
    int h = idx & (HH - 1);
    int b = idx >> 10;
    float carry = g_fn_scan(h0[b * HH + h]);
#pragma unroll
    for (int c = 0; c < NC; ++c) {
        int s = (b * NC + c) * HH + h;
        g_carry[s] = carry;
        carry = fmaf(g_A[s], carry, g_Bc[s]);
    }
}

// ---------------- scan pass 3: apply carries, write output ----------------
__global__ __launch_bounds__(256)
void scan_apply(float* __restrict__ out) {
    int idx = blockIdx.x * blockDim.x + threadIdx.x;   // (b, c, h)
    int h = idx & (HH - 1);
    int c = (idx >> 10) & (NC - 1);
    int b = idx >> 15;
    size_t base = ((size_t)(b * TT + c * CL)) * HH + h;
    float hc = g_carry[(b * NC + c) * HH + h];
#pragma unroll 8
    for (int i = 0; i < CL; ++i) {
        float a = g_a[base + (size_t)i * HH];
        float bb = g_b[base + (size_t)i * HH];
        hc = fmaf(a, hc, bb);
        out[base + (size_t)i * HH] = hc;
    }
}

extern "C" void kernel_launch(void* const* d_in, const int* in_sizes, int n_in,
                              void* d_out, int out_size) {
    const float* x  = (const float*)d_in[0];
    const float* h0 = (const float*)d_in[1];
    const float* Wz = (const float*)d_in[2];
    const float* bz = (const float*)d_in[3];
    const float* Wh = (const float*)d_in[4];
    const float* bh = (const float*)d_in[5];
    float* out = (float*)d_out;

    __half *x16, *wz, *wh;
    cudaGetSymbolAddress((void**)&x16, g_x16);
    cudaGetSymbolAddress((void**)&wz,  g_wz);
    cudaGetSymbolAddress((void**)&wh,  g_wh);

    cvt_kernel<<<(int)(((size_t)MTOT * II) / 1024), 256>>>(x, x16);
    cvt_kernel<<<(HH * II) / 1024, 256>>>(Wz, wz);
    cvt_kernel<<<(HH * II) / 1024, 256>>>(Wh, wh);

    cudaFuncSetAttribute(gemm_mma_kernel, cudaFuncAttributeMaxDynamicSharedMemorySize, SMEM_TOTAL);
    dim3 ggrid(HH / 64, MTOT / 128);   // x = n-block (16), y = m-block (256)
    gemm_mma_kernel<<<ggrid, 256, SMEM_TOTAL>>>(bz, bh);

    scan_chunk_combine<<<(BB * HH) / 256, 256>>>(h0);
    scan_apply<<<(BB * NC * HH) / 256, 256>>>(out);
}